// round 14
// baseline (speedup 1.0000x reference)
#include <cuda_runtime.h>
#include <cuda_fp16.h>
#include <cuda_bf16.h>

// Problem constants
#define N_USERS 100000
#define N_ITEMS 100000
#define N_NODES 200000
#define D       64
#define NNZ     3200000
#define BATCH   500000

#define ND4 (N_NODES * D / 4)            // 3.2M 4-elem chunks
#define SCAN_BLK 256
#define NBLK_SCAN ((N_NODES + SCAN_BLK - 1) / SCAN_BLK)   // 782
#define PERM_SIZE (NBLK_SCAN * SCAN_BLK)                  // 200192
#define NQUADS    (PERM_SIZE / 4)                         // 50048

// out = C0*b + C1*Ab + C2*A^2 b + C3*A^3 b
#define C0 1.6f
#define C1 1.12f
#define C2 0.768f
#define C3 0.512f

// Edge value quantization: val in [0, 1/16), 14 bits -> step 1/262144.
#define VAL_SCALE   262144.0f
#define VAL_INV     (1.0f / 262144.0f)

// epack capacity: padded edges ~= NNZ * 1.11 ~= 3.6M; 5M is generous.
#define EPACK_ENTRIES 5000000
#define EPACK_U4      (EPACK_ENTRIES / 4)    // 1.25M uint4

// Static device scratch (allocation-free rule).
__device__ __half             g_h[3][N_NODES * D];   // h0=b, h1=Ab, h2=A^2 b
__device__ __half             g_out[N_NODES * D];    // 25.6 MB fp16
__device__ int                g_count[N_NODES];      // zeroed by scan each launch
__device__ int                g_rowstart[N_NODES];   // GLOBAL epack offset per row
__device__ int                g_perm[PERM_SIZE];     // degree-sorted row order
__device__ int                g_quadstart[NQUADS];   // epack offset of quad
__device__ int                g_quadP[NQUADS];       // padded per-row count of quad
__device__ unsigned long long g_status[NBLK_SCAN];   // lookback state (zeroed each launch)
__device__ unsigned char      g_rank[NNZ];           // within-row rank
__device__ uint4              g_epack4[EPACK_U4];    // col(18b)|valq(14b)<<18, padded CSR

#define ELEM_BLOCKS ((ND4 + 255) / 256)              // 12500
#define EDGE_BLOCKS ((NNZ + 255) / 256)              // 12500
#define ZERO_BLOCKS ((EPACK_U4 + 255) / 256)         // 4883

// ---------------------------------------------------------------------------
// Phase A (fused): blocks [0,25000) interleave table->h0 conversion (even)
// with row histogram + rank recording (odd); blocks [25000,...) zero the
// epack pad region and the lookback status array (overlaps with atomics).
// ---------------------------------------------------------------------------
__global__ __launch_bounds__(256) void init_hist_kernel(
    const float* __restrict__ user_table,
    const float* __restrict__ item_table,
    const int*   __restrict__ rows)
{
    int b = blockIdx.x;
    if (b < 2 * ELEM_BLOCKS) {
        if ((b & 1) == 0) {
            int i = (b >> 1) * 256 + threadIdx.x;   // 4-elem chunk index
            if (i >= ND4) return;
            const int u4 = N_USERS * D / 4;
            float4 v;
            if (i < u4) v = reinterpret_cast<const float4*>(user_table)[i];
            else        v = reinterpret_cast<const float4*>(item_table)[i - u4];
            __half2 lo = __floats2half2_rn(v.x, v.y);
            __half2 hi = __floats2half2_rn(v.z, v.w);
            uint2 packed;
            packed.x = *reinterpret_cast<unsigned*>(&lo);
            packed.y = *reinterpret_cast<unsigned*>(&hi);
            reinterpret_cast<uint2*>(g_h[0])[i] = packed;
        } else {
            int e = (b >> 1) * 256 + threadIdx.x;
            if (e >= NNZ) return;
            int rank = atomicAdd(&g_count[rows[e]], 1);
            g_rank[e] = (unsigned char)rank;
        }
    } else {
        int z = b - 2 * ELEM_BLOCKS;
        if (z == 0) {
            for (int idx = threadIdx.x; idx < NBLK_SCAN; idx += 256)
                g_status[idx] = 0ull;
        }
        int idx = z * 256 + threadIdx.x;
        if (idx < EPACK_U4)
            g_epack4[idx] = make_uint4(0u, 0u, 0u, 0u);
    }
}

// ---------------------------------------------------------------------------
// Scan: per block — counting-sort rows by degree, quad-pad to ceil4 of quad
// max, local prefix + decoupled lookback for global offsets.
// ---------------------------------------------------------------------------
__global__ __launch_bounds__(256, 8) void scan_kernel()
{
    __shared__ int sm[256];
    __shared__ int hist[256];
    __shared__ int sc[256];
    __shared__ int srtc[256];
    __shared__ int prow[256];
    __shared__ unsigned long long s_excl;
    int t = threadIdx.x;
    int bid = blockIdx.x;
    int i = bid * 256 + t;
    bool valid = (i < N_NODES);
    int c = valid ? g_count[i] : 0;
    if (valid) g_count[i] = 0;

    // counting sort ascending by degree
    int key = min(c, 255);
    hist[t] = 0;
    __syncthreads();
    atomicAdd(&hist[key], 1);
    __syncthreads();
    int hv = hist[t];
    sc[t] = hv;
    __syncthreads();
    for (int off = 1; off < 256; off <<= 1) {
        int x = (t >= off) ? sc[t - off] : 0;
        __syncthreads();
        sc[t] += x;
        __syncthreads();
    }
    hist[t] = sc[t] - hv;
    __syncthreads();
    int pos = atomicAdd(&hist[key], 1);
    prow[pos] = valid ? i : -1;
    srtc[pos] = c;
    __syncthreads();

    // quad-padded count at sorted position t (quad max is at t|3, ascending)
    int P = (srtc[t | 3] + 3) & ~3;
    sm[t] = P;
    __syncthreads();
    for (int off = 1; off < 256; off <<= 1) {
        int x = (t >= off) ? sm[t - off] : 0;
        __syncthreads();
        sm[t] += x;
        __syncthreads();
    }
    int lexcl = sm[t] - P;
    int T_b = sm[255];

    // publish aggregate / prefix, then windowed lookback (warp 0)
    if (t == 0) {
        unsigned long long st = (bid == 0)
            ? ((2ull << 62) | (unsigned long long)T_b)
            : ((1ull << 62) | (unsigned long long)T_b);
        atomicExch(&g_status[bid], st);
        if (bid == 0) s_excl = 0ull;
    }
    if (t < 32 && bid > 0) {
        unsigned long long excl = 0;
        int base = bid - 1;
        for (;;) {
            int p = base - t;
            unsigned long long s;
            if (p >= 0) {
                do { s = atomicAdd(&g_status[p], 0ull); } while ((s >> 62) == 0ull);
            } else {
                s = (2ull << 62);    // virtual prefix 0 before block 0
            }
            unsigned pm = __ballot_sync(0xffffffffu, (s >> 62) == 2ull);
            unsigned long long val = s & 0x3FFFFFFFFFFFFFFFull;
            unsigned long long contrib;
            if (pm) {
                int first = __ffs(pm) - 1;       // nearest predecessor w/ prefix
                contrib = (t <= first) ? val : 0ull;
            } else {
                contrib = val;
            }
            #pragma unroll
            for (int o = 16; o; o >>= 1)
                contrib += __shfl_xor_sync(0xffffffffu, contrib, o);
            excl += contrib;
            if (pm) break;
            base -= 32;
        }
        if (t == 0) {
            atomicExch(&g_status[bid],
                       (2ull << 62) | (excl + (unsigned long long)T_b));
            s_excl = excl;
        }
    }
    __syncthreads();
    int start = (int)s_excl + lexcl;

    int r = prow[t];
    if (r >= 0) g_rowstart[r] = start;
    g_perm[bid * 256 + t] = r;
    if ((t & 3) == 0) {
        int q = (bid * 256 + t) >> 2;
        g_quadstart[q] = start;
        g_quadP[q] = P;
    }
}

// ---------------------------------------------------------------------------
// scatter: p = rowstart[row] + rank -> packed 4-byte edge. One random load
// per edge. Pad slots never written (stay zero).
// ---------------------------------------------------------------------------
__global__ __launch_bounds__(256) void scatter_kernel(
    const int*   __restrict__ rows,
    const int*   __restrict__ cols,
    const float* __restrict__ vals)
{
    unsigned* __restrict__ ep = reinterpret_cast<unsigned*>(g_epack4);
    int t = blockIdx.x * 256 + threadIdx.x;
    if (t * 8 >= NNZ) return;
    int4   r0 = reinterpret_cast<const int4*>(rows)[2 * t];
    int4   r1 = reinterpret_cast<const int4*>(rows)[2 * t + 1];
    int4   c0 = reinterpret_cast<const int4*>(cols)[2 * t];
    int4   c1 = reinterpret_cast<const int4*>(cols)[2 * t + 1];
    float4 v0 = reinterpret_cast<const float4*>(vals)[2 * t];
    float4 v1 = reinterpret_cast<const float4*>(vals)[2 * t + 1];
    uint2  k8 = reinterpret_cast<const uint2*>(g_rank)[t];

    int   r[8] = {r0.x, r0.y, r0.z, r0.w, r1.x, r1.y, r1.z, r1.w};
    int   c[8] = {c0.x, c0.y, c0.z, c0.w, c1.x, c1.y, c1.z, c1.w};
    float v[8] = {v0.x, v0.y, v0.z, v0.w, v1.x, v1.y, v1.z, v1.w};
    int   k[8];
    k[0] =  k8.x        & 255; k[1] = (k8.x >> 8)  & 255;
    k[2] = (k8.x >> 16) & 255; k[3] = (k8.x >> 24) & 255;
    k[4] =  k8.y        & 255; k[5] = (k8.y >> 8)  & 255;
    k[6] = (k8.y >> 16) & 255; k[7] = (k8.y >> 24) & 255;

    int p[8];
    #pragma unroll
    for (int m = 0; m < 8; ++m)
        p[m] = g_rowstart[r[m]] + k[m];
    #pragma unroll
    for (int m = 0; m < 8; ++m) {
        unsigned vq = (unsigned)__float2int_rn(v[m] * VAL_SCALE);
        if (vq > 16383u) vq = 16383u;
        ep[p[m]] = (unsigned)c[m] | (vq << 18);
    }
}

// ---------------------------------------------------------------------------
// gather-SpMM with cp.async smem staging.
// One quad (4 equal-padded rows) per warp; 8-lane groups; lane owns 16B of
// its row. Batches of 4 edges are staged into shared memory via cp.async.cg
// (in-flight data lives in SMEM, not registers -> MLP 8/warp at ~36 regs,
// 6 blocks/SM). Double-buffered: stage batch k+1, wait on batch k, consume
// from SMEM via LDS.128. Uniform trip counts (padded CSR) -> no predication,
// no cross-thread sharing -> no __syncthreads needed.
// ---------------------------------------------------------------------------
__device__ __forceinline__ void cp16(unsigned saddr, const void* gptr)
{
    asm volatile("cp.async.cg.shared.global [%0], [%1], 16;"
                 :: "r"(saddr), "l"(gptr));
}

__device__ __forceinline__ void accum_packed(unsigned long long* acc,
                                             const uint4& x, unsigned long long vv)
{
    const unsigned* xs = reinterpret_cast<const unsigned*>(&x);
    #pragma unroll
    for (int k = 0; k < 4; ++k) {
        float2 f = __half22float2(*reinterpret_cast<const __half2*>(&xs[k]));
        unsigned long long xf;
        asm("mov.b64 %0, {%1, %2};" : "=l"(xf) : "f"(f.x), "f"(f.y));
        asm("fma.rn.f32x2 %0, %1, %2, %0;" : "+l"(acc[k]) : "l"(xf), "l"(vv));
    }
}

template <int LAYER, int LAST>
__global__ __launch_bounds__(256, 6) void spmm_kernel()
{
    // staging: [buf 0/1][edge 0..3][thread 0..255] x 16 bytes = 32 KB
    __shared__ __align__(16) char stage_smem[2][4][256 * 16];
    const __half* __restrict__ src = g_h[LAYER];
    int W    = (blockIdx.x * 256 + threadIdx.x) >> 5;   // warp = quad index
    int lane = threadIdx.x & 31;
    int grp  = lane >> 3;                                // 0..3: row group
    int subl = lane & 7;                                 // lane within group
    int qs = g_quadstart[W];                             // uniform per warp
    int P  = g_quadP[W];                                 // uniform per warp
    int r  = g_perm[W * 4 + grp];
    int iters = P >> 2;
    int j4 = (qs + grp * P) >> 2;                        // uint4-aligned

    const uint4* __restrict__ ep4 = g_epack4;
    unsigned sbase = (unsigned)__cvta_generic_to_shared(&stage_smem[0][0][0])
                   + threadIdx.x * 16;

    unsigned long long acc[4] = {0ull, 0ull, 0ull, 0ull};

    uint4 qc = make_uint4(0u, 0u, 0u, 0u);
    if (iters > 0) {
        qc = ep4[j4];
        cp16(sbase + 0 * 4096, src + (size_t)(qc.x & 0x3FFFFu) * D + subl * 8);
        cp16(sbase + 1 * 4096, src + (size_t)(qc.y & 0x3FFFFu) * D + subl * 8);
        cp16(sbase + 2 * 4096, src + (size_t)(qc.z & 0x3FFFFu) * D + subl * 8);
        cp16(sbase + 3 * 4096, src + (size_t)(qc.w & 0x3FFFFu) * D + subl * 8);
    }
    asm volatile("cp.async.commit_group;");

    for (int it = 0; it < iters; ++it) {
        uint4 qn = make_uint4(0u, 0u, 0u, 0u);
        if (it + 1 < iters) {
            qn = ep4[j4 + it + 1];
            unsigned sb = sbase + (((it + 1) & 1) ? 16384u : 0u);
            cp16(sb + 0 * 4096, src + (size_t)(qn.x & 0x3FFFFu) * D + subl * 8);
            cp16(sb + 1 * 4096, src + (size_t)(qn.y & 0x3FFFFu) * D + subl * 8);
            cp16(sb + 2 * 4096, src + (size_t)(qn.z & 0x3FFFFu) * D + subl * 8);
            cp16(sb + 3 * 4096, src + (size_t)(qn.w & 0x3FFFFu) * D + subl * 8);
        }
        asm volatile("cp.async.commit_group;");

        // decode current batch values while batch-it data is landing
        float v0 = (float)(qc.x >> 18);   // integer-scaled; VAL_INV in epilogue
        float v1 = (float)(qc.y >> 18);
        float v2 = (float)(qc.z >> 18);
        float v3 = (float)(qc.w >> 18);
        unsigned long long vv0, vv1, vv2, vv3;
        asm("mov.b64 %0, {%1, %1};" : "=l"(vv0) : "f"(v0));
        asm("mov.b64 %0, {%1, %1};" : "=l"(vv1) : "f"(v1));
        asm("mov.b64 %0, {%1, %1};" : "=l"(vv2) : "f"(v2));
        asm("mov.b64 %0, {%1, %1};" : "=l"(vv3) : "f"(v3));

        asm volatile("cp.async.wait_group 1;" ::: "memory");

        char* bufp = &stage_smem[it & 1][0][threadIdx.x * 16];
        uint4 x0 = *reinterpret_cast<const uint4*>(bufp + 0 * 4096);
        uint4 x1 = *reinterpret_cast<const uint4*>(bufp + 1 * 4096);
        uint4 x2 = *reinterpret_cast<const uint4*>(bufp + 2 * 4096);
        uint4 x3 = *reinterpret_cast<const uint4*>(bufp + 3 * 4096);
        accum_packed(acc, x0, vv0);
        accum_packed(acc, x1, vv1);
        accum_packed(acc, x2, vv2);
        accum_packed(acc, x3, vv3);
        qc = qn;
    }

    if (r < 0) return;
    float a[8];
    #pragma unroll
    for (int k = 0; k < 4; ++k)
        asm("mov.b64 {%0, %1}, %2;" : "=f"(a[2 * k]), "=f"(a[2 * k + 1])
                                    : "l"(acc[k]));

    size_t off = (size_t)r * D + subl * 8;   // halves; 16B-aligned
    if (LAST) {
        uint4 b4  = *reinterpret_cast<const uint4*>(g_h[0] + off);
        uint4 y14 = *reinterpret_cast<const uint4*>(g_h[1] + off);
        uint4 y24 = *reinterpret_cast<const uint4*>(g_h[2] + off);
        const unsigned* bp  = reinterpret_cast<const unsigned*>(&b4);
        const unsigned* y1p = reinterpret_cast<const unsigned*>(&y14);
        const unsigned* y2p = reinterpret_cast<const unsigned*>(&y24);
        uint4 outv;
        unsigned* op = reinterpret_cast<unsigned*>(&outv);
        const float c3s = C3 * VAL_INV;
        #pragma unroll
        for (int k = 0; k < 4; ++k) {
            float2 fb = __half22float2(*reinterpret_cast<const __half2*>(&bp[k]));
            float2 f1 = __half22float2(*reinterpret_cast<const __half2*>(&y1p[k]));
            float2 f2 = __half22float2(*reinterpret_cast<const __half2*>(&y2p[k]));
            float ox = C0 * fb.x + C1 * f1.x + C2 * f2.x + c3s * a[2 * k];
            float oy = C0 * fb.y + C1 * f1.y + C2 * f2.y + c3s * a[2 * k + 1];
            __half2 h = __floats2half2_rn(ox, oy);
            op[k] = *reinterpret_cast<unsigned*>(&h);
        }
        *reinterpret_cast<uint4*>(g_out + off) = outv;
    } else {
        uint4 outv;
        unsigned* op = reinterpret_cast<unsigned*>(&outv);
        #pragma unroll
        for (int k = 0; k < 4; ++k) {
            __half2 h = __floats2half2_rn(a[2 * k] * VAL_INV,
                                          a[2 * k + 1] * VAL_INV);
            op[k] = *reinterpret_cast<unsigned*>(&h);
        }
        *reinterpret_cast<uint4*>(g_h[LAYER + 1] + off) = outv;
    }
}

// ---------------------------------------------------------------------------
// dot: result[p] = dot(out[users[p]], out[N_USERS+items[p]]) / 16
// ---------------------------------------------------------------------------
__device__ __forceinline__ float dot8h(uint4 a, uint4 b)
{
    float s = 0.f;
    float2 fa, fb;
    fa = __half22float2(*reinterpret_cast<__half2*>(&a.x));
    fb = __half22float2(*reinterpret_cast<__half2*>(&b.x));
    s += fa.x * fb.x + fa.y * fb.y;
    fa = __half22float2(*reinterpret_cast<__half2*>(&a.y));
    fb = __half22float2(*reinterpret_cast<__half2*>(&b.y));
    s += fa.x * fb.x + fa.y * fb.y;
    fa = __half22float2(*reinterpret_cast<__half2*>(&a.z));
    fb = __half22float2(*reinterpret_cast<__half2*>(&b.z));
    s += fa.x * fb.x + fa.y * fb.y;
    fa = __half22float2(*reinterpret_cast<__half2*>(&a.w));
    fb = __half22float2(*reinterpret_cast<__half2*>(&b.w));
    s += fa.x * fb.x + fa.y * fb.y;
    return s;
}

__global__ __launch_bounds__(256) void dot_kernel(
    const int* __restrict__ users,
    const int* __restrict__ items,
    float*     __restrict__ result)
{
    int t = blockIdx.x * 256 + threadIdx.x;
    int p    = t >> 2;
    int lane = t & 3;
    if (p >= BATCH) return;
    int u  = users[p];
    int it = items[p];
    const uint4* pa = reinterpret_cast<const uint4*>(g_out + (size_t)u * D);
    const uint4* pb = reinterpret_cast<const uint4*>(g_out + (size_t)(N_USERS + it) * D);
    uint4 a0 = pa[lane];
    uint4 a1 = pa[lane + 4];
    uint4 b0 = pb[lane];
    uint4 b1 = pb[lane + 4];
    float s = dot8h(a0, b0) + dot8h(a1, b1);
    s += __shfl_xor_sync(0xffffffffu, s, 1);
    s += __shfl_xor_sync(0xffffffffu, s, 2);
    if (lane == 0) result[p] = s * 0.0625f;
}

// ---------------------------------------------------------------------------
extern "C" void kernel_launch(void* const* d_in, const int* in_sizes, int n_in,
                              void* d_out, int out_size)
{
    const float* user_table = (const float*)d_in[0];
    const float* item_table = (const float*)d_in[1];
    const int*   rows       = (const int*)  d_in[2];
    const int*   cols       = (const int*)  d_in[3];
    const float* vals       = (const float*)d_in[4];
    const int*   users      = (const int*)  d_in[5];
    const int*   items      = (const int*)  d_in[6];
    float*       result     = (float*)d_out;
    (void)in_sizes; (void)n_in; (void)out_size;

    const int ih_blocks      = 2 * ELEM_BLOCKS + ZERO_BLOCKS; // 29883
    const int spmm_blocks    = NQUADS / 8;                    // 6256
    const int dot_blocks     = (BATCH * 4 + 255) / 256;       // 7813
    const int scatter_blocks = (NNZ / 8 + 255) / 256;         // 1563

    init_hist_kernel<<<ih_blocks, 256>>>(user_table, item_table, rows);
    scan_kernel<<<NBLK_SCAN, SCAN_BLK>>>();
    scatter_kernel<<<scatter_blocks, 256>>>(rows, cols, vals);
    spmm_kernel<0, 0><<<spmm_blocks, 256>>>();
    spmm_kernel<1, 0><<<spmm_blocks, 256>>>();
    spmm_kernel<2, 1><<<spmm_blocks, 256>>>();
    dot_kernel<<<dot_blocks, 256>>>(users, items, result);
}

// round 15
// speedup vs baseline: 1.5846x; 1.5846x over previous
#include <cuda_runtime.h>
#include <cuda_fp16.h>
#include <cuda_bf16.h>

// Problem constants
#define N_USERS 100000
#define N_ITEMS 100000
#define N_NODES 200000
#define D       64
#define NNZ     3200000
#define BATCH   500000

#define ND4 (N_NODES * D / 4)            // 3.2M 4-elem chunks
#define SCAN_BLK 256
#define NBLK_SCAN ((N_NODES + SCAN_BLK - 1) / SCAN_BLK)   // 782
#define PERM_SIZE (NBLK_SCAN * SCAN_BLK)                  // 200192
#define NQUADS    (PERM_SIZE / 4)                         // 50048

// out = C0*b + C1*Ab + C2*A^2 b + C3*A^3 b
#define C0 1.6f
#define C1 1.12f
#define C2 0.768f
#define C3 0.512f

// Edge value quantization: val in [0, 1/16), 14 bits -> step 1/262144.
#define VAL_SCALE   262144.0f
#define VAL_INV     (1.0f / 262144.0f)

// epack capacity: padded edges ~= NNZ * 1.11 ~= 3.6M; 5M is generous.
#define EPACK_ENTRIES 5000000
#define EPACK_U4      (EPACK_ENTRIES / 4)    // 1.25M uint4

// Static device scratch (allocation-free rule).
// g_count / g_status are restored each launch by the kernels that consume
// them; g_rowstart is rebuilt by scan every launch (scatter consumes it
// destructively as the per-row fill cursor).
__device__ __half             g_h[3][N_NODES * D];   // h0=b, h1=Ab, h2=A^2 b
__device__ __half             g_out[N_NODES * D];    // 25.6 MB fp16
__device__ int                g_count[N_NODES];      // zeroed by scan each launch
__device__ int                g_rowstart[N_NODES];   // global epack offset / fill cursor
__device__ int                g_perm[PERM_SIZE];     // degree-sorted row order
__device__ int                g_quadstart[NQUADS];   // epack offset of quad
__device__ int                g_quadP[NQUADS];       // padded per-row count of quad
__device__ unsigned long long g_status[NBLK_SCAN];   // lookback state (zeroed each launch)
__device__ uint4              g_epack4[EPACK_U4];    // col(18b)|valq(14b)<<18, padded CSR

#define ELEM_BLOCKS ((ND4 + 255) / 256)              // 12500
#define EDGE_BLOCKS ((NNZ + 255) / 256)              // 12500
#define ZERO_BLOCKS ((EPACK_U4 + 255) / 256)         // 4883

// ---------------------------------------------------------------------------
// Phase A (fused): blocks [0,25000) interleave table->h0 conversion (even)
// with the row-degree histogram (odd, pure RED atomics — no return value);
// blocks [25000,...) zero the epack pad region and the lookback status array.
// ---------------------------------------------------------------------------
__global__ __launch_bounds__(256) void init_hist_kernel(
    const float* __restrict__ user_table,
    const float* __restrict__ item_table,
    const int*   __restrict__ rows)
{
    int b = blockIdx.x;
    if (b < 2 * ELEM_BLOCKS) {
        if ((b & 1) == 0) {
            int i = (b >> 1) * 256 + threadIdx.x;   // 4-elem chunk index
            if (i >= ND4) return;
            const int u4 = N_USERS * D / 4;
            float4 v;
            if (i < u4) v = reinterpret_cast<const float4*>(user_table)[i];
            else        v = reinterpret_cast<const float4*>(item_table)[i - u4];
            __half2 lo = __floats2half2_rn(v.x, v.y);
            __half2 hi = __floats2half2_rn(v.z, v.w);
            uint2 packed;
            packed.x = *reinterpret_cast<unsigned*>(&lo);
            packed.y = *reinterpret_cast<unsigned*>(&hi);
            reinterpret_cast<uint2*>(g_h[0])[i] = packed;
        } else {
            int e = (b >> 1) * 256 + threadIdx.x;
            if (e >= NNZ) return;
            atomicAdd(&g_count[rows[e]], 1);    // return unused -> RED
        }
    } else {
        int z = b - 2 * ELEM_BLOCKS;
        if (z == 0) {
            for (int idx = threadIdx.x; idx < NBLK_SCAN; idx += 256)
                g_status[idx] = 0ull;
        }
        int idx = z * 256 + threadIdx.x;
        if (idx < EPACK_U4)
            g_epack4[idx] = make_uint4(0u, 0u, 0u, 0u);
    }
}

// ---------------------------------------------------------------------------
// Scan: per block — counting-sort rows by degree, quad-pad to ceil4 of quad
// max, local prefix + decoupled lookback for global offsets.
// ---------------------------------------------------------------------------
__global__ __launch_bounds__(256, 8) void scan_kernel()
{
    __shared__ int sm[256];
    __shared__ int hist[256];
    __shared__ int sc[256];
    __shared__ int srtc[256];
    __shared__ int prow[256];
    __shared__ unsigned long long s_excl;
    int t = threadIdx.x;
    int bid = blockIdx.x;
    int i = bid * 256 + t;
    bool valid = (i < N_NODES);
    int c = valid ? g_count[i] : 0;
    if (valid) g_count[i] = 0;

    // counting sort ascending by degree
    int key = min(c, 255);
    hist[t] = 0;
    __syncthreads();
    atomicAdd(&hist[key], 1);
    __syncthreads();
    int hv = hist[t];
    sc[t] = hv;
    __syncthreads();
    for (int off = 1; off < 256; off <<= 1) {
        int x = (t >= off) ? sc[t - off] : 0;
        __syncthreads();
        sc[t] += x;
        __syncthreads();
    }
    hist[t] = sc[t] - hv;
    __syncthreads();
    int pos = atomicAdd(&hist[key], 1);
    prow[pos] = valid ? i : -1;
    srtc[pos] = c;
    __syncthreads();

    // quad-padded count at sorted position t (quad max is at t|3, ascending)
    int P = (srtc[t | 3] + 3) & ~3;
    sm[t] = P;
    __syncthreads();
    for (int off = 1; off < 256; off <<= 1) {
        int x = (t >= off) ? sm[t - off] : 0;
        __syncthreads();
        sm[t] += x;
        __syncthreads();
    }
    int lexcl = sm[t] - P;
    int T_b = sm[255];

    // publish aggregate / prefix, then windowed lookback (warp 0)
    if (t == 0) {
        unsigned long long st = (bid == 0)
            ? ((2ull << 62) | (unsigned long long)T_b)
            : ((1ull << 62) | (unsigned long long)T_b);
        atomicExch(&g_status[bid], st);
        if (bid == 0) s_excl = 0ull;
    }
    if (t < 32 && bid > 0) {
        unsigned long long excl = 0;
        int base = bid - 1;
        for (;;) {
            int p = base - t;
            unsigned long long s;
            if (p >= 0) {
                do { s = atomicAdd(&g_status[p], 0ull); } while ((s >> 62) == 0ull);
            } else {
                s = (2ull << 62);    // virtual prefix 0 before block 0
            }
            unsigned pm = __ballot_sync(0xffffffffu, (s >> 62) == 2ull);
            unsigned long long val = s & 0x3FFFFFFFFFFFFFFFull;
            unsigned long long contrib;
            if (pm) {
                int first = __ffs(pm) - 1;       // nearest predecessor w/ prefix
                contrib = (t <= first) ? val : 0ull;
            } else {
                contrib = val;
            }
            #pragma unroll
            for (int o = 16; o; o >>= 1)
                contrib += __shfl_xor_sync(0xffffffffu, contrib, o);
            excl += contrib;
            if (pm) break;
            base -= 32;
        }
        if (t == 0) {
            atomicExch(&g_status[bid],
                       (2ull << 62) | (excl + (unsigned long long)T_b));
            s_excl = excl;
        }
    }
    __syncthreads();
    int start = (int)s_excl + lexcl;

    int r = prow[t];
    if (r >= 0) g_rowstart[r] = start;
    g_perm[bid * 256 + t] = r;
    if ((t & 3) == 0) {
        int q = (bid * 256 + t) >> 2;
        g_quadstart[q] = start;
        g_quadP[q] = P;
    }
}

// ---------------------------------------------------------------------------
// scatter: p = atomicAdd(&g_rowstart[row], 1) -> packed 4-byte edge.
// One L2 atomic per edge (replaces the rank load + rowstart load); the
// cursor array is rebuilt by scan on every launch. Pad slots stay zero.
// ---------------------------------------------------------------------------
__global__ __launch_bounds__(256) void scatter_kernel(
    const int*   __restrict__ rows,
    const int*   __restrict__ cols,
    const float* __restrict__ vals)
{
    unsigned* __restrict__ ep = reinterpret_cast<unsigned*>(g_epack4);
    int t = blockIdx.x * 256 + threadIdx.x;
    if (t * 8 >= NNZ) return;
    int4   r0 = reinterpret_cast<const int4*>(rows)[2 * t];
    int4   r1 = reinterpret_cast<const int4*>(rows)[2 * t + 1];
    int4   c0 = reinterpret_cast<const int4*>(cols)[2 * t];
    int4   c1 = reinterpret_cast<const int4*>(cols)[2 * t + 1];
    float4 v0 = reinterpret_cast<const float4*>(vals)[2 * t];
    float4 v1 = reinterpret_cast<const float4*>(vals)[2 * t + 1];

    int   r[8] = {r0.x, r0.y, r0.z, r0.w, r1.x, r1.y, r1.z, r1.w};
    int   c[8] = {c0.x, c0.y, c0.z, c0.w, c1.x, c1.y, c1.z, c1.w};
    float v[8] = {v0.x, v0.y, v0.z, v0.w, v1.x, v1.y, v1.z, v1.w};

    int p[8];
    #pragma unroll
    for (int m = 0; m < 8; ++m)                      // 8 independent atomics
        p[m] = atomicAdd(&g_rowstart[r[m]], 1);
    #pragma unroll
    for (int m = 0; m < 8; ++m) {
        unsigned vq = (unsigned)__float2int_rn(v[m] * VAL_SCALE);
        if (vq > 16383u) vq = 16383u;
        ep[p[m]] = (unsigned)c[m] | (vq << 18);
    }
}

// ---------------------------------------------------------------------------
// gather-SpMM (R13 proven-best form): y = A * src. One quad (4 equal-padded
// rows) per warp, 8-lane groups, lane owns uint4 (16B = 8 halves). Uniform
// trip count, no predicates, single LDG.128 for 4 edge descriptors. Packed
// f32x2 FMA accumulators.
// ---------------------------------------------------------------------------
__device__ __forceinline__ void accum_packed(unsigned long long* acc,
                                             const uint4& x, unsigned long long vv)
{
    const unsigned* xs = reinterpret_cast<const unsigned*>(&x);
    #pragma unroll
    for (int k = 0; k < 4; ++k) {
        float2 f = __half22float2(*reinterpret_cast<const __half2*>(&xs[k]));
        unsigned long long xf;
        asm("mov.b64 %0, {%1, %2};" : "=l"(xf) : "f"(f.x), "f"(f.y));
        asm("fma.rn.f32x2 %0, %1, %2, %0;" : "+l"(acc[k]) : "l"(xf), "l"(vv));
    }
}

template <int LAYER, int LAST>
__global__ __launch_bounds__(256, 6) void spmm_kernel()
{
    const __half* __restrict__ src = g_h[LAYER];
    int W    = (blockIdx.x * 256 + threadIdx.x) >> 5;   // warp = quad index
    int lane = threadIdx.x & 31;
    int grp  = lane >> 3;                                // 0..3: row group
    int subl = lane & 7;                                 // lane within group
    int qs = g_quadstart[W];                             // uniform per warp
    int P  = g_quadP[W];                                 // uniform per warp
    int r  = g_perm[W * 4 + grp];
    int iters = P >> 2;
    int j4 = (qs + grp * P) >> 2;                        // uint4-aligned

    unsigned long long acc[4] = {0ull, 0ull, 0ull, 0ull};
    const uint4* __restrict__ ep4 = g_epack4;
    for (int it = 0; it < iters; ++it) {
        uint4 q = ep4[j4 + it];                          // 4 descriptors, 1 LDG
        uint4 x0 = *reinterpret_cast<const uint4*>(
                       src + (size_t)(q.x & 0x3FFFFu) * D + subl * 8);
        uint4 x1 = *reinterpret_cast<const uint4*>(
                       src + (size_t)(q.y & 0x3FFFFu) * D + subl * 8);
        uint4 x2 = *reinterpret_cast<const uint4*>(
                       src + (size_t)(q.z & 0x3FFFFu) * D + subl * 8);
        uint4 x3 = *reinterpret_cast<const uint4*>(
                       src + (size_t)(q.w & 0x3FFFFu) * D + subl * 8);
        float v0 = (float)(q.x >> 18);   // integer-scaled; VAL_INV in epilogue
        float v1 = (float)(q.y >> 18);
        float v2 = (float)(q.z >> 18);
        float v3 = (float)(q.w >> 18);
        unsigned long long vv0, vv1, vv2, vv3;
        asm("mov.b64 %0, {%1, %1};" : "=l"(vv0) : "f"(v0));
        asm("mov.b64 %0, {%1, %1};" : "=l"(vv1) : "f"(v1));
        asm("mov.b64 %0, {%1, %1};" : "=l"(vv2) : "f"(v2));
        asm("mov.b64 %0, {%1, %1};" : "=l"(vv3) : "f"(v3));
        accum_packed(acc, x0, vv0);
        accum_packed(acc, x1, vv1);
        accum_packed(acc, x2, vv2);
        accum_packed(acc, x3, vv3);
    }

    if (r < 0) return;
    float a[8];
    #pragma unroll
    for (int k = 0; k < 4; ++k)
        asm("mov.b64 {%0, %1}, %2;" : "=f"(a[2 * k]), "=f"(a[2 * k + 1])
                                    : "l"(acc[k]));

    size_t off = (size_t)r * D + subl * 8;   // halves; 16B-aligned
    if (LAST) {
        uint4 b4  = *reinterpret_cast<const uint4*>(g_h[0] + off);
        uint4 y14 = *reinterpret_cast<const uint4*>(g_h[1] + off);
        uint4 y24 = *reinterpret_cast<const uint4*>(g_h[2] + off);
        const unsigned* bp  = reinterpret_cast<const unsigned*>(&b4);
        const unsigned* y1p = reinterpret_cast<const unsigned*>(&y14);
        const unsigned* y2p = reinterpret_cast<const unsigned*>(&y24);
        uint4 outv;
        unsigned* op = reinterpret_cast<unsigned*>(&outv);
        const float c3s = C3 * VAL_INV;
        #pragma unroll
        for (int k = 0; k < 4; ++k) {
            float2 fb = __half22float2(*reinterpret_cast<const __half2*>(&bp[k]));
            float2 f1 = __half22float2(*reinterpret_cast<const __half2*>(&y1p[k]));
            float2 f2 = __half22float2(*reinterpret_cast<const __half2*>(&y2p[k]));
            float ox = C0 * fb.x + C1 * f1.x + C2 * f2.x + c3s * a[2 * k];
            float oy = C0 * fb.y + C1 * f1.y + C2 * f2.y + c3s * a[2 * k + 1];
            __half2 h = __floats2half2_rn(ox, oy);
            op[k] = *reinterpret_cast<unsigned*>(&h);
        }
        *reinterpret_cast<uint4*>(g_out + off) = outv;
    } else {
        uint4 outv;
        unsigned* op = reinterpret_cast<unsigned*>(&outv);
        #pragma unroll
        for (int k = 0; k < 4; ++k) {
            __half2 h = __floats2half2_rn(a[2 * k] * VAL_INV,
                                          a[2 * k + 1] * VAL_INV);
            op[k] = *reinterpret_cast<unsigned*>(&h);
        }
        *reinterpret_cast<uint4*>(g_h[LAYER + 1] + off) = outv;
    }
}

// ---------------------------------------------------------------------------
// dot: result[p] = dot(out[users[p]], out[N_USERS+items[p]]) / 16
// ---------------------------------------------------------------------------
__device__ __forceinline__ float dot8h(uint4 a, uint4 b)
{
    float s = 0.f;
    float2 fa, fb;
    fa = __half22float2(*reinterpret_cast<__half2*>(&a.x));
    fb = __half22float2(*reinterpret_cast<__half2*>(&b.x));
    s += fa.x * fb.x + fa.y * fb.y;
    fa = __half22float2(*reinterpret_cast<__half2*>(&a.y));
    fb = __half22float2(*reinterpret_cast<__half2*>(&b.y));
    s += fa.x * fb.x + fa.y * fb.y;
    fa = __half22float2(*reinterpret_cast<__half2*>(&a.z));
    fb = __half22float2(*reinterpret_cast<__half2*>(&b.z));
    s += fa.x * fb.x + fa.y * fb.y;
    fa = __half22float2(*reinterpret_cast<__half2*>(&a.w));
    fb = __half22float2(*reinterpret_cast<__half2*>(&b.w));
    s += fa.x * fb.x + fa.y * fb.y;
    return s;
}

__global__ __launch_bounds__(256) void dot_kernel(
    const int* __restrict__ users,
    const int* __restrict__ items,
    float*     __restrict__ result)
{
    int t = blockIdx.x * 256 + threadIdx.x;
    int p    = t >> 2;
    int lane = t & 3;
    if (p >= BATCH) return;
    int u  = users[p];
    int it = items[p];
    const uint4* pa = reinterpret_cast<const uint4*>(g_out + (size_t)u * D);
    const uint4* pb = reinterpret_cast<const uint4*>(g_out + (size_t)(N_USERS + it) * D);
    uint4 a0 = pa[lane];
    uint4 a1 = pa[lane + 4];
    uint4 b0 = pb[lane];
    uint4 b1 = pb[lane + 4];
    float s = dot8h(a0, b0) + dot8h(a1, b1);
    s += __shfl_xor_sync(0xffffffffu, s, 1);
    s += __shfl_xor_sync(0xffffffffu, s, 2);
    if (lane == 0) result[p] = s * 0.0625f;
}

// ---------------------------------------------------------------------------
extern "C" void kernel_launch(void* const* d_in, const int* in_sizes, int n_in,
                              void* d_out, int out_size)
{
    const float* user_table = (const float*)d_in[0];
    const float* item_table = (const float*)d_in[1];
    const int*   rows       = (const int*)  d_in[2];
    const int*   cols       = (const int*)  d_in[3];
    const float* vals       = (const float*)d_in[4];
    const int*   users      = (const int*)  d_in[5];
    const int*   items      = (const int*)  d_in[6];
    float*       result     = (float*)d_out;
    (void)in_sizes; (void)n_in; (void)out_size;

    const int ih_blocks      = 2 * ELEM_BLOCKS + ZERO_BLOCKS; // 29883
    const int spmm_blocks    = NQUADS / 8;                    // 6256
    const int dot_blocks     = (BATCH * 4 + 255) / 256;       // 7813
    const int scatter_blocks = (NNZ / 8 + 255) / 256;         // 1563

    init_hist_kernel<<<ih_blocks, 256>>>(user_table, item_table, rows);
    scan_kernel<<<NBLK_SCAN, SCAN_BLK>>>();
    scatter_kernel<<<scatter_blocks, 256>>>(rows, cols, vals);
    spmm_kernel<0, 0><<<spmm_blocks, 256>>>();
    spmm_kernel<1, 0><<<spmm_blocks, 256>>>();
    spmm_kernel<2, 1><<<spmm_blocks, 256>>>();
    dot_kernel<<<dot_blocks, 256>>>(users, items, result);
}

// round 16
// speedup vs baseline: 1.8068x; 1.1403x over previous
#include <cuda_runtime.h>
#include <cuda_fp16.h>
#include <cuda_bf16.h>

// Problem constants
#define N_USERS 100000
#define N_ITEMS 100000
#define N_NODES 200000
#define D       64
#define NNZ     3200000
#define BATCH   500000

#define ND4 (N_NODES * D / 4)            // 3.2M 4-elem chunks
#define SCAN_BLK 256
#define NBLK_SCAN ((N_NODES + SCAN_BLK - 1) / SCAN_BLK)   // 782
#define PERM_SIZE (NBLK_SCAN * SCAN_BLK)                  // 200192
#define NQUADS    (PERM_SIZE / 4)                         // 50048

// out = C0*b + C1*Ab + C2*A^2 b + C3*A^3 b
#define C0 1.6f
#define C1 1.12f
#define C2 0.768f
#define C3 0.512f

// epack entry: col(18b) | fp16_bits(val)(14b)<<18.
// vals < 1/16 => fp16 exponent field <= 10 => bit pattern < 0x4000 (14 bits).
// Pad slots are zero => col 0, val +0.0 (harmless).
#define EPACK_ENTRIES 5000000
#define EPACK_U4      (EPACK_ENTRIES / 4)    // 1.25M uint4

// Static device scratch (allocation-free rule).
__device__ __half             g_h[3][N_NODES * D];   // h0=b, h1=Ab, h2=A^2 b
__device__ __half             g_out[N_NODES * D];    // 25.6 MB fp16
__device__ int                g_count[N_NODES];      // zeroed by scan each launch
__device__ int                g_rowstart[N_NODES];   // GLOBAL epack offset per row
__device__ int                g_perm[PERM_SIZE];     // degree-sorted row order
__device__ int                g_quadstart[NQUADS];   // epack offset of quad
__device__ int                g_quadP[NQUADS];       // padded per-row count of quad
__device__ unsigned long long g_status[NBLK_SCAN];   // lookback state (zeroed each launch)
__device__ unsigned char      g_rank[NNZ];           // within-row rank
__device__ uint4              g_epack4[EPACK_U4];    // padded CSR edges

#define ELEM_BLOCKS ((ND4 + 255) / 256)              // 12500
#define EDGE_BLOCKS ((NNZ + 255) / 256)              // 12500
#define ZERO_BLOCKS ((EPACK_U4 + 255) / 256)         // 4883

// ---------------------------------------------------------------------------
// Phase A (fused): blocks [0,25000) interleave table->h0 conversion (even)
// with row histogram + rank recording (odd); blocks [25000,...) zero the
// epack pad region and the lookback status array.
// ---------------------------------------------------------------------------
__global__ __launch_bounds__(256) void init_hist_kernel(
    const float* __restrict__ user_table,
    const float* __restrict__ item_table,
    const int*   __restrict__ rows)
{
    int b = blockIdx.x;
    if (b < 2 * ELEM_BLOCKS) {
        if ((b & 1) == 0) {
            int i = (b >> 1) * 256 + threadIdx.x;   // 4-elem chunk index
            if (i >= ND4) return;
            const int u4 = N_USERS * D / 4;
            float4 v;
            if (i < u4) v = reinterpret_cast<const float4*>(user_table)[i];
            else        v = reinterpret_cast<const float4*>(item_table)[i - u4];
            __half2 lo = __floats2half2_rn(v.x, v.y);
            __half2 hi = __floats2half2_rn(v.z, v.w);
            uint2 packed;
            packed.x = *reinterpret_cast<unsigned*>(&lo);
            packed.y = *reinterpret_cast<unsigned*>(&hi);
            reinterpret_cast<uint2*>(g_h[0])[i] = packed;
        } else {
            int e = (b >> 1) * 256 + threadIdx.x;
            if (e >= NNZ) return;
            int rank = atomicAdd(&g_count[rows[e]], 1);
            g_rank[e] = (unsigned char)rank;
        }
    } else {
        int z = b - 2 * ELEM_BLOCKS;
        if (z == 0) {
            for (int idx = threadIdx.x; idx < NBLK_SCAN; idx += 256)
                g_status[idx] = 0ull;
        }
        int idx = z * 256 + threadIdx.x;
        if (idx < EPACK_U4)
            g_epack4[idx] = make_uint4(0u, 0u, 0u, 0u);
    }
}

// ---------------------------------------------------------------------------
// Scan: per block — counting-sort rows by degree, quad-pad to ceil4 of quad
// max, local prefix + decoupled lookback for global offsets.
// ---------------------------------------------------------------------------
__global__ __launch_bounds__(256, 8) void scan_kernel()
{
    __shared__ int sm[256];
    __shared__ int hist[256];
    __shared__ int sc[256];
    __shared__ int srtc[256];
    __shared__ int prow[256];
    __shared__ unsigned long long s_excl;
    int t = threadIdx.x;
    int bid = blockIdx.x;
    int i = bid * 256 + t;
    bool valid = (i < N_NODES);
    int c = valid ? g_count[i] : 0;
    if (valid) g_count[i] = 0;

    // counting sort ascending by degree
    int key = min(c, 255);
    hist[t] = 0;
    __syncthreads();
    atomicAdd(&hist[key], 1);
    __syncthreads();
    int hv = hist[t];
    sc[t] = hv;
    __syncthreads();
    for (int off = 1; off < 256; off <<= 1) {
        int x = (t >= off) ? sc[t - off] : 0;
        __syncthreads();
        sc[t] += x;
        __syncthreads();
    }
    hist[t] = sc[t] - hv;
    __syncthreads();
    int pos = atomicAdd(&hist[key], 1);
    prow[pos] = valid ? i : -1;
    srtc[pos] = c;
    __syncthreads();

    // quad-padded count at sorted position t (quad max is at t|3, ascending)
    int P = (srtc[t | 3] + 3) & ~3;
    sm[t] = P;
    __syncthreads();
    for (int off = 1; off < 256; off <<= 1) {
        int x = (t >= off) ? sm[t - off] : 0;
        __syncthreads();
        sm[t] += x;
        __syncthreads();
    }
    int lexcl = sm[t] - P;
    int T_b = sm[255];

    // publish aggregate / prefix, then windowed lookback (warp 0)
    if (t == 0) {
        unsigned long long st = (bid == 0)
            ? ((2ull << 62) | (unsigned long long)T_b)
            : ((1ull << 62) | (unsigned long long)T_b);
        atomicExch(&g_status[bid], st);
        if (bid == 0) s_excl = 0ull;
    }
    if (t < 32 && bid > 0) {
        unsigned long long excl = 0;
        int base = bid - 1;
        for (;;) {
            int p = base - t;
            unsigned long long s;
            if (p >= 0) {
                do { s = atomicAdd(&g_status[p], 0ull); } while ((s >> 62) == 0ull);
            } else {
                s = (2ull << 62);    // virtual prefix 0 before block 0
            }
            unsigned pm = __ballot_sync(0xffffffffu, (s >> 62) == 2ull);
            unsigned long long val = s & 0x3FFFFFFFFFFFFFFFull;
            unsigned long long contrib;
            if (pm) {
                int first = __ffs(pm) - 1;       // nearest predecessor w/ prefix
                contrib = (t <= first) ? val : 0ull;
            } else {
                contrib = val;
            }
            #pragma unroll
            for (int o = 16; o; o >>= 1)
                contrib += __shfl_xor_sync(0xffffffffu, contrib, o);
            excl += contrib;
            if (pm) break;
            base -= 32;
        }
        if (t == 0) {
            atomicExch(&g_status[bid],
                       (2ull << 62) | (excl + (unsigned long long)T_b));
            s_excl = excl;
        }
    }
    __syncthreads();
    int start = (int)s_excl + lexcl;

    int r = prow[t];
    if (r >= 0) g_rowstart[r] = start;
    g_perm[bid * 256 + t] = r;
    if ((t & 3) == 0) {
        int q = (bid * 256 + t) >> 2;
        g_quadstart[q] = start;
        g_quadP[q] = P;
    }
}

// ---------------------------------------------------------------------------
// scatter: p = rowstart[row] + rank -> packed 4-byte edge with the weight
// stored as raw fp16 bits (14 bits). No atomics. Pad slots stay zero.
// ---------------------------------------------------------------------------
__global__ __launch_bounds__(256) void scatter_kernel(
    const int*   __restrict__ rows,
    const int*   __restrict__ cols,
    const float* __restrict__ vals)
{
    unsigned* __restrict__ ep = reinterpret_cast<unsigned*>(g_epack4);
    int t = blockIdx.x * 256 + threadIdx.x;
    if (t * 8 >= NNZ) return;
    int4   r0 = reinterpret_cast<const int4*>(rows)[2 * t];
    int4   r1 = reinterpret_cast<const int4*>(rows)[2 * t + 1];
    int4   c0 = reinterpret_cast<const int4*>(cols)[2 * t];
    int4   c1 = reinterpret_cast<const int4*>(cols)[2 * t + 1];
    float4 v0 = reinterpret_cast<const float4*>(vals)[2 * t];
    float4 v1 = reinterpret_cast<const float4*>(vals)[2 * t + 1];
    uint2  k8 = reinterpret_cast<const uint2*>(g_rank)[t];

    int   r[8] = {r0.x, r0.y, r0.z, r0.w, r1.x, r1.y, r1.z, r1.w};
    int   c[8] = {c0.x, c0.y, c0.z, c0.w, c1.x, c1.y, c1.z, c1.w};
    float v[8] = {v0.x, v0.y, v0.z, v0.w, v1.x, v1.y, v1.z, v1.w};
    int   k[8];
    k[0] =  k8.x        & 255; k[1] = (k8.x >> 8)  & 255;
    k[2] = (k8.x >> 16) & 255; k[3] = (k8.x >> 24) & 255;
    k[4] =  k8.y        & 255; k[5] = (k8.y >> 8)  & 255;
    k[6] = (k8.y >> 16) & 255; k[7] = (k8.y >> 24) & 255;

    int p[8];
    #pragma unroll
    for (int m = 0; m < 8; ++m)
        p[m] = g_rowstart[r[m]] + k[m];
    #pragma unroll
    for (int m = 0; m < 8; ++m) {
        __half hv = __float2half_rn(v[m]);            // < 1/16 -> bits < 0x4000
        unsigned hb = (unsigned)__half_as_ushort(hv);
        ep[p[m]] = (unsigned)c[m] | (hb << 18);
    }
}

// ---------------------------------------------------------------------------
// gather-SpMM with native HFMA2 accumulation.
// One quad (4 equal-padded rows) per warp, 8-lane groups, lane owns uint4
// (16B = 8 halves). Per edge: decode weight (shift + dup into half2) and
// 4 HFMA2 — no H2F conversions, no pack MOVs, no descale (weights are true
// fp16 values). Mid-layer epilogue is a raw accumulator store.
// ---------------------------------------------------------------------------
__device__ __forceinline__ void accum_h2(unsigned* acc, const uint4& x, unsigned vv)
{
    const unsigned* xs = reinterpret_cast<const unsigned*>(&x);
    #pragma unroll
    for (int k = 0; k < 4; ++k) {
        __half2 a = *reinterpret_cast<const __half2*>(&acc[k]);
        __half2 xh = *reinterpret_cast<const __half2*>(&xs[k]);
        __half2 vh = *reinterpret_cast<const __half2*>(&vv);
        a = __hfma2(xh, vh, a);
        acc[k] = *reinterpret_cast<unsigned*>(&a);
    }
}

template <int LAYER, int LAST>
__global__ __launch_bounds__(256, 6) void spmm_kernel()
{
    const __half* __restrict__ src = g_h[LAYER];
    int W    = (blockIdx.x * 256 + threadIdx.x) >> 5;   // warp = quad index
    int lane = threadIdx.x & 31;
    int grp  = lane >> 3;                                // 0..3: row group
    int subl = lane & 7;                                 // lane within group
    int qs = g_quadstart[W];                             // uniform per warp
    int P  = g_quadP[W];                                 // uniform per warp
    int r  = g_perm[W * 4 + grp];
    int iters = P >> 2;
    int j4 = (qs + grp * P) >> 2;                        // uint4-aligned

    unsigned acc[4] = {0u, 0u, 0u, 0u};                  // 4 x half2 = 8 halves
    const uint4* __restrict__ ep4 = g_epack4;
    for (int it = 0; it < iters; ++it) {
        uint4 q = ep4[j4 + it];                          // 4 descriptors, 1 LDG
        uint4 x0 = *reinterpret_cast<const uint4*>(
                       src + (size_t)(q.x & 0x3FFFFu) * D + subl * 8);
        uint4 x1 = *reinterpret_cast<const uint4*>(
                       src + (size_t)(q.y & 0x3FFFFu) * D + subl * 8);
        uint4 x2 = *reinterpret_cast<const uint4*>(
                       src + (size_t)(q.z & 0x3FFFFu) * D + subl * 8);
        uint4 x3 = *reinterpret_cast<const uint4*>(
                       src + (size_t)(q.w & 0x3FFFFu) * D + subl * 8);
        unsigned h0 = q.x >> 18, h1 = q.y >> 18, h2 = q.z >> 18, h3 = q.w >> 18;
        unsigned vv0 = h0 | (h0 << 16);
        unsigned vv1 = h1 | (h1 << 16);
        unsigned vv2 = h2 | (h2 << 16);
        unsigned vv3 = h3 | (h3 << 16);
        accum_h2(acc, x0, vv0);
        accum_h2(acc, x1, vv1);
        accum_h2(acc, x2, vv2);
        accum_h2(acc, x3, vv3);
    }

    if (r < 0) return;
    size_t off = (size_t)r * D + subl * 8;   // halves; 16B-aligned
    if (LAST) {
        uint4 b4  = *reinterpret_cast<const uint4*>(g_h[0] + off);
        uint4 y14 = *reinterpret_cast<const uint4*>(g_h[1] + off);
        uint4 y24 = *reinterpret_cast<const uint4*>(g_h[2] + off);
        const unsigned* bp  = reinterpret_cast<const unsigned*>(&b4);
        const unsigned* y1p = reinterpret_cast<const unsigned*>(&y14);
        const unsigned* y2p = reinterpret_cast<const unsigned*>(&y24);
        uint4 outv;
        unsigned* op = reinterpret_cast<unsigned*>(&outv);
        #pragma unroll
        for (int k = 0; k < 4; ++k) {
            float2 fb = __half22float2(*reinterpret_cast<const __half2*>(&bp[k]));
            float2 f1 = __half22float2(*reinterpret_cast<const __half2*>(&y1p[k]));
            float2 f2 = __half22float2(*reinterpret_cast<const __half2*>(&y2p[k]));
            float2 fa = __half22float2(*reinterpret_cast<const __half2*>(&acc[k]));
            float ox = C0 * fb.x + C1 * f1.x + C2 * f2.x + C3 * fa.x;
            float oy = C0 * fb.y + C1 * f1.y + C2 * f2.y + C3 * fa.y;
            __half2 h = __floats2half2_rn(ox, oy);
            op[k] = *reinterpret_cast<unsigned*>(&h);
        }
        *reinterpret_cast<uint4*>(g_out + off) = outv;
    } else {
        uint4 outv;
        unsigned* op = reinterpret_cast<unsigned*>(&outv);
        #pragma unroll
        for (int k = 0; k < 4; ++k) op[k] = acc[k];      // raw fp16 store
        *reinterpret_cast<uint4*>(g_h[LAYER + 1] + off) = outv;
    }
}

// ---------------------------------------------------------------------------
// dot: result[p] = dot(out[users[p]], out[N_USERS+items[p]]) / 16
// ---------------------------------------------------------------------------
__device__ __forceinline__ float dot8h(uint4 a, uint4 b)
{
    float s = 0.f;
    float2 fa, fb;
    fa = __half22float2(*reinterpret_cast<__half2*>(&a.x));
    fb = __half22float2(*reinterpret_cast<__half2*>(&b.x));
    s += fa.x * fb.x + fa.y * fb.y;
    fa = __half22float2(*reinterpret_cast<__half2*>(&a.y));
    fb = __half22float2(*reinterpret_cast<__half2*>(&b.y));
    s += fa.x * fb.x + fa.y * fb.y;
    fa = __half22float2(*reinterpret_cast<__half2*>(&a.z));
    fb = __half22float2(*reinterpret_cast<__half2*>(&b.z));
    s += fa.x * fb.x + fa.y * fb.y;
    fa = __half22float2(*reinterpret_cast<__half2*>(&a.w));
    fb = __half22float2(*reinterpret_cast<__half2*>(&b.w));
    s += fa.x * fb.x + fa.y * fb.y;
    return s;
}

__global__ __launch_bounds__(256) void dot_kernel(
    const int* __restrict__ users,
    const int* __restrict__ items,
    float*     __restrict__ result)
{
    int t = blockIdx.x * 256 + threadIdx.x;
    int p    = t >> 2;
    int lane = t & 3;
    if (p >= BATCH) return;
    int u  = users[p];
    int it = items[p];
    const uint4* pa = reinterpret_cast<const uint4*>(g_out + (size_t)u * D);
    const uint4* pb = reinterpret_cast<const uint4*>(g_out + (size_t)(N_USERS + it) * D);
    uint4 a0 = pa[lane];
    uint4 a1 = pa[lane + 4];
    uint4 b0 = pb[lane];
    uint4 b1 = pb[lane + 4];
    float s = dot8h(a0, b0) + dot8h(a1, b1);
    s += __shfl_xor_sync(0xffffffffu, s, 1);
    s += __shfl_xor_sync(0xffffffffu, s, 2);
    if (lane == 0) result[p] = s * 0.0625f;
}

// ---------------------------------------------------------------------------
extern "C" void kernel_launch(void* const* d_in, const int* in_sizes, int n_in,
                              void* d_out, int out_size)
{
    const float* user_table = (const float*)d_in[0];
    const float* item_table = (const float*)d_in[1];
    const int*   rows       = (const int*)  d_in[2];
    const int*   cols       = (const int*)  d_in[3];
    const float* vals       = (const float*)d_in[4];
    const int*   users      = (const int*)  d_in[5];
    const int*   items      = (const int*)  d_in[6];
    float*       result     = (float*)d_out;
    (void)in_sizes; (void)n_in; (void)out_size;

    const int ih_blocks      = 2 * ELEM_BLOCKS + ZERO_BLOCKS; // 29883
    const int spmm_blocks    = NQUADS / 8;                    // 6256
    const int dot_blocks     = (BATCH * 4 + 255) / 256;       // 7813
    const int scatter_blocks = (NNZ / 8 + 255) / 256;         // 1563

    init_hist_kernel<<<ih_blocks, 256>>>(user_table, item_table, rows);
    scan_kernel<<<NBLK_SCAN, SCAN_BLK>>>();
    scatter_kernel<<<scatter_blocks, 256>>>(rows, cols, vals);
    spmm_kernel<0, 0><<<spmm_blocks, 256>>>();
    spmm_kernel<1, 0><<<spmm_blocks, 256>>>();
    spmm_kernel<2, 1><<<spmm_blocks, 256>>>();
    dot_kernel<<<dot_blocks, 256>>>(users, items, result);
}